// round 6
// baseline (speedup 1.0000x reference)
#include <cuda_runtime.h>
#include <cuda_bf16.h>

// ---------------------------------------------------------------------------
// DownSample: FPS(64->32 strokes) + gathers + conv(1x3,s=2,p=1) 128->256 +
// BatchNorm(batch stats, fused partial sums) + tanh-GELU.
//
// Output layout in d_out (float32):
//   [0        , 524288)    sparse_out      [64,256,32]
//   [524288   , 17301504)  dense_out       [64,256,1024]
//   [17301504 , 17367040)  stk_coor_sampled[64,32,32]
// ---------------------------------------------------------------------------

#define N_STK      64
#define N_HALF     32
#define N_PNT      64
#define COOR_EMB   32
#define BS         64
#define C_IN       128
#define C_OUT      256
#define SP_EMB     256
#define NBLK       (BS * N_HALF)      // 2048 conv blocks

__device__ __align__(16) int    g_fps_idx[BS * N_HALF];
__device__ __align__(16) unsigned long long g_wp[C_IN * C_OUT * 4]; // dup pairs [i][o][k0,k1,k2,pad]
__device__ __align__(16) float  g_y[(size_t)BS * C_OUT * 1024];     // conv out (64 MB)
__device__ __align__(16) float2 g_ps[NBLK * C_OUT];                 // per-block (sum, sumsq)
__device__ __align__(16) float  g_scale[C_OUT];
__device__ __align__(16) float  g_shift[C_OUT];

// ---------------- f32x2 packed helpers (sm_103a) ----------------
__device__ __forceinline__ void unpack2(unsigned long long v, float& x, float& y) {
    asm("mov.b64 {%0, %1}, %2;" : "=f"(x), "=f"(y) : "l"(v));
}
__device__ __forceinline__ unsigned long long fma2(unsigned long long a,
                                                   unsigned long long b,
                                                   unsigned long long c) {
    unsigned long long d;
    asm("fma.rn.f32x2 %0, %1, %2, %3;" : "=l"(d) : "l"(a), "l"(b), "l"(c));
    return d;
}

// ---------------- K1: farthest point sampling -------------------
__global__ void fps_kernel(const float* __restrict__ coor, float* __restrict__ coor_out) {
    int b = blockIdx.x;
    int n = threadIdx.x;

    float p[COOR_EMB];
    const float4* src = (const float4*)(coor + ((size_t)b * N_STK + n) * COOR_EMB);
#pragma unroll
    for (int q = 0; q < COOR_EMB / 4; q++) {
        float4 v = src[q];
        p[4 * q + 0] = v.x; p[4 * q + 1] = v.y; p[4 * q + 2] = v.z; p[4 * q + 3] = v.w;
    }

    __shared__ __align__(16) float cen[COOR_EMB];
    __shared__ float sd[N_STK];
    __shared__ int   si[N_STK];

    float dist = 1e10f;
    int farthest = 0;

    for (int it = 0; it < N_HALF; it++) {
        if (n == 0) g_fps_idx[b * N_HALF + it] = farthest;
        if (n == farthest) {
            float* co = coor_out + ((size_t)b * N_HALF + it) * COOR_EMB;
#pragma unroll
            for (int c = 0; c < COOR_EMB; c++) { cen[c] = p[c]; co[c] = p[c]; }
        }
        __syncthreads();

        float d = 0.f;
#pragma unroll
        for (int c = 0; c < COOR_EMB; c++) {
            float df = p[c] - cen[c];
            d = fmaf(df, df, d);
        }
        dist = fminf(dist, d);

        sd[n] = dist; si[n] = n;
        __syncthreads();
#pragma unroll
        for (int st = 32; st > 0; st >>= 1) {
            if (n < st) {
                float dv = sd[n + st]; int iv = si[n + st];
                if (dv > sd[n] || (dv == sd[n] && iv < si[n])) { sd[n] = dv; si[n] = iv; }
            }
            __syncthreads();
        }
        farthest = si[0];
        __syncthreads();
    }
}

// ---------------- K2: fused sparse gather + weight dup-transpose ----
__global__ void prep_kernel(const float* __restrict__ sp, const float* __restrict__ w,
                            float* __restrict__ sparse_out) {
    int blk = blockIdx.x;
    int tid = threadIdx.x;
    if (blk < 2048) {
        int gid = blk * 256 + tid;               // BS*SP_EMB*N_HALF = 524288
        int s = gid & 31;
        int e = (gid >> 5) & 255;
        int b = gid >> 13;
        int sid = g_fps_idx[b * N_HALF + s];
        sparse_out[gid] = sp[((size_t)b * SP_EMB + e) * N_STK + sid];
    } else {
        int idx = (blk - 2048) * 256 + tid;      // C_IN*C_OUT*4 = 131072
        int k = idx & 3;
        int o = (idx >> 2) & 255;
        int i = idx >> 10;
        float wv = (k < 3) ? w[o * (C_IN * 3) + i * 3 + k] : 0.f;
        unsigned int u = __float_as_uint(wv);
        g_wp[idx] = (unsigned long long)u | ((unsigned long long)u << 32);
    }
}

// ---------------- K3: gathered strided conv (deferred shift) -----
// block = (stroke s, batch b); 256 threads; thread t owns channel t.
// y[p'] = w0*v[p'-1] + w1*u[p'] + w2*v[p'] summed over i  (u=even, v=odd taps)
// Aligned accumulation:  Z_j += w1*U_j + w2*V_j ;  A_j += w0*V_j
// Epilogue shift: y[2j] = Z_j.lo + A_{j-1}.hi ; y[2j+1] = Z_j.hi + A_j.lo
#define ROWP 36
#define CSTEP(j, Uv, Vv)            \
    Z[j] = fma2(Uv, W1, Z[j]);      \
    Z[j] = fma2(Vv, W2, Z[j]);      \
    A[j] = fma2(Vv, W0, A[j]);

__global__ __launch_bounds__(256, 2) void conv_kernel(const float* __restrict__ dense,
                                                      const float* __restrict__ bias) {
    __shared__ __align__(16) float sbuf[2 * C_IN * ROWP];   // 36.9 KB
    float* su = sbuf;
    float* sv = sbuf + C_IN * ROWP;

    int s = blockIdx.x;
    int b = blockIdx.y;
    int t = threadIdx.x;

    int sid = g_fps_idx[b * N_HALF + s];
    const float* src = dense + (size_t)b * C_IN * (N_STK * N_PNT) + sid * N_PNT;

    // fill: 256 threads, each loads half a channel row (32 floats), deinterleaves
    {
        int i = t >> 1, h = t & 1;
        const float4* r = (const float4*)(src + (size_t)i * (N_STK * N_PNT) + h * 32);
        float* pu = su + i * ROWP + h * 16;
        float* pv = sv + i * ROWP + h * 16;
#pragma unroll
        for (int q = 0; q < 8; q++) {
            float4 x = r[q];
            pu[2 * q]     = x.x;
            pu[2 * q + 1] = x.z;
            pv[2 * q]     = x.y;
            pv[2 * q + 1] = x.w;
        }
    }
    __syncthreads();

    unsigned long long Z[16], A[16];
#pragma unroll
    for (int j = 0; j < 16; j++) { Z[j] = 0ULL; A[j] = 0ULL; }

    for (int i = 0; i < C_IN; i++) {
        size_t wi = ((size_t)(i << 8) + t) * 4;
        ulonglong2 w01 = *(const ulonglong2*)(g_wp + wi);
        unsigned long long W0 = w01.x, W1 = w01.y, W2 = g_wp[wi + 2];
        const float* ru = su + i * ROWP;
        const float* rv = sv + i * ROWP;
#pragma unroll
        for (int c = 0; c < 4; c++) {
            ulonglong2 Ua = *(const ulonglong2*)(ru + 8 * c);
            ulonglong2 Va = *(const ulonglong2*)(rv + 8 * c);
            ulonglong2 Ub = *(const ulonglong2*)(ru + 8 * c + 4);
            ulonglong2 Vb = *(const ulonglong2*)(rv + 8 * c + 4);
            CSTEP(4 * c + 0, Ua.x, Va.x)
            CSTEP(4 * c + 1, Ua.y, Va.y)
            CSTEP(4 * c + 2, Ub.x, Vb.x)
            CSTEP(4 * c + 3, Ub.y, Vb.y)
        }
    }
    __syncthreads();

    // epilogue: shift-combine + bias; per-channel BN partials
    float bv = bias[t];
    float* sy = sbuf;    // 256*33 = 8448 floats <= 9216 available
    float ph = 0.f, s0 = 0.f, q0 = 0.f;
#pragma unroll
    for (int j = 0; j < 16; j++) {
        float zl, zh, al, ah;
        unpack2(Z[j], zl, zh); unpack2(A[j], al, ah);
        float y0 = zl + ph + bv;
        float y1 = zh + al + bv;
        ph = ah;
        sy[t * 33 + 2 * j]     = y0;
        sy[t * 33 + 2 * j + 1] = y1;
        s0 += y0 + y1;
        q0 = fmaf(y0, y0, q0); q0 = fmaf(y1, y1, q0);
    }
    int k = b * N_HALF + s;
    g_ps[(size_t)k * C_OUT + t] = make_float2(s0, q0);
    __syncthreads();

    float* dst = g_y + (size_t)b * C_OUT * 1024 + s * 32;
    for (int e = t; e < C_OUT * 32; e += 256) {
        int o2 = e >> 5, p = e & 31;
        dst[(size_t)o2 * 1024 + p] = sy[o2 * 33 + p];
    }
}

// ---------------- K4: BN finish (reduce partials) ---------------
__global__ void bn_finish(const float* __restrict__ gamma, const float* __restrict__ beta) {
    int o = blockIdx.x;
    int t = threadIdx.x;  // 256
    float S = 0.f, Q = 0.f;
    for (int k = t; k < NBLK; k += 256) {
        float2 p = g_ps[(size_t)k * C_OUT + o];
        S += p.x; Q += p.y;
    }
    __shared__ float rs[256], rq[256];
    rs[t] = S; rq[t] = Q;
    __syncthreads();
    for (int st = 128; st > 0; st >>= 1) {
        if (t < st) { rs[t] += rs[t + st]; rq[t] += rq[t + st]; }
        __syncthreads();
    }
    if (t == 0) {
        const float inv_n = 1.f / 65536.f;
        float mean = rs[0] * inv_n;
        float var  = rq[0] * inv_n - mean * mean;
        float r    = rsqrtf(var + 1e-5f);
        float sc   = gamma[o] * r;
        g_scale[o] = sc;
        g_shift[o] = beta[o] - mean * sc;
    }
}

// ---------------- K5: normalize + GELU --------------------------
__device__ __forceinline__ float gelu_f(float x) {
    float z = 0.7978845608028654f * fmaf(0.044715f * x, x * x, x);
    float e = __expf(2.f * z);
    float th = 1.f - __fdividef(2.f, e + 1.f);
    return 0.5f * x * (1.f + th);
}

__global__ void bn_gelu(float* __restrict__ out) {
    int i = blockIdx.x * blockDim.x + threadIdx.x;
    if (i < (BS * C_OUT * 1024) / 4) {
        float4 v = ((const float4*)g_y)[i];
        int o = (i >> 8) & 255;
        float sc = g_scale[o], sh = g_shift[o];
        v.x = gelu_f(fmaf(v.x, sc, sh));
        v.y = gelu_f(fmaf(v.y, sc, sh));
        v.z = gelu_f(fmaf(v.z, sc, sh));
        v.w = gelu_f(fmaf(v.w, sc, sh));
        ((float4*)out)[i] = v;
    }
}

// ---------------- launch ----------------------------------------
extern "C" void kernel_launch(void* const* d_in, const int* in_sizes, int n_in,
                              void* d_out, int out_size) {
    const float* sparse_fea = (const float*)d_in[0];   // [64,256,64]
    const float* dense_fea  = (const float*)d_in[1];   // [64,128,4096]
    const float* stk_coor   = (const float*)d_in[2];   // [64,64,32]
    const float* conv_w     = (const float*)d_in[3];   // [256,128,1,3]
    const float* conv_b     = (const float*)d_in[4];   // [256]
    const float* bn_gamma   = (const float*)d_in[5];   // [256]
    const float* bn_beta    = (const float*)d_in[6];   // [256]

    float* out = (float*)d_out;
    float* sparse_out = out;                            // 524288
    float* dense_out  = out + 524288;                   // 16777216
    float* coor_out   = out + 524288 + 16777216;        // 65536

    fps_kernel<<<BS, N_STK>>>(stk_coor, coor_out);
    prep_kernel<<<2048 + 512, 256>>>(sparse_fea, conv_w, sparse_out);
    conv_kernel<<<dim3(N_HALF, BS), 256>>>(dense_fea, conv_b);
    bn_finish<<<C_OUT, 256>>>(bn_gamma, bn_beta);
    bn_gelu<<<(BS * C_OUT * 1024 / 4 + 255) / 256, 256>>>(dense_out);
}

// round 7
// speedup vs baseline: 1.3292x; 1.3292x over previous
#include <cuda_runtime.h>
#include <cuda_bf16.h>

// ---------------------------------------------------------------------------
// DownSample: FPS(64->32 strokes) + gathers + conv(1x3,s=2,p=1) 128->256 +
// BatchNorm(batch stats, fused partials) + tanh-GELU.
//
// Output layout in d_out (float32):
//   [0        , 524288)    sparse_out      [64,256,32]
//   [524288   , 17301504)  dense_out       [64,256,1024]
//   [17301504 , 17367040)  stk_coor_sampled[64,32,32]
// ---------------------------------------------------------------------------

#define N_STK      64
#define N_HALF     32
#define N_PNT      64
#define COOR_EMB   32
#define BS         64
#define C_IN       128
#define C_OUT      256
#define SP_EMB     256
#define NBLK       (BS * N_HALF)      // 2048 conv blocks

__device__ __align__(16) int    g_fps_idx[BS * N_HALF];
__device__ __align__(16) float  g_wt[C_IN * C_OUT * 4];         // [i][o][k0,k1,k2,pad]
__device__ __align__(16) float  g_y[(size_t)BS * C_OUT * 1024]; // conv out (64 MB)
__device__ __align__(16) float2 g_ps[NBLK * C_OUT];             // per-block (sum, sumsq)
__device__ __align__(16) float  g_scale[C_OUT];
__device__ __align__(16) float  g_shift[C_OUT];

// ---------------- f32x2 packed helpers (sm_103a) ----------------
__device__ __forceinline__ unsigned long long pack2(float x, float y) {
    unsigned long long r;
    asm("mov.b64 %0, {%1, %2};" : "=l"(r) : "f"(x), "f"(y));
    return r;
}
__device__ __forceinline__ void unpack2(unsigned long long v, float& x, float& y) {
    asm("mov.b64 {%0, %1}, %2;" : "=f"(x), "=f"(y) : "l"(v));
}
__device__ __forceinline__ unsigned long long fma2(unsigned long long a,
                                                   unsigned long long b,
                                                   unsigned long long c) {
    unsigned long long d;
    asm("fma.rn.f32x2 %0, %1, %2, %3;" : "=l"(d) : "l"(a), "l"(b), "l"(c));
    return d;
}

// ---------------- K1: farthest point sampling -------------------
__global__ void fps_kernel(const float* __restrict__ coor, float* __restrict__ coor_out) {
    int b = blockIdx.x;
    int n = threadIdx.x;

    float p[COOR_EMB];
    const float4* src = (const float4*)(coor + ((size_t)b * N_STK + n) * COOR_EMB);
#pragma unroll
    for (int q = 0; q < COOR_EMB / 4; q++) {
        float4 v = src[q];
        p[4 * q + 0] = v.x; p[4 * q + 1] = v.y; p[4 * q + 2] = v.z; p[4 * q + 3] = v.w;
    }

    __shared__ __align__(16) float cen[COOR_EMB];
    __shared__ float sd[N_STK];
    __shared__ int   si[N_STK];

    float dist = 1e10f;
    int farthest = 0;

    for (int it = 0; it < N_HALF; it++) {
        if (n == 0) g_fps_idx[b * N_HALF + it] = farthest;
        if (n == farthest) {
            float* co = coor_out + ((size_t)b * N_HALF + it) * COOR_EMB;
#pragma unroll
            for (int c = 0; c < COOR_EMB; c++) { cen[c] = p[c]; co[c] = p[c]; }
        }
        __syncthreads();

        float d = 0.f;
#pragma unroll
        for (int c = 0; c < COOR_EMB; c++) {
            float df = p[c] - cen[c];
            d = fmaf(df, df, d);
        }
        dist = fminf(dist, d);

        sd[n] = dist; si[n] = n;
        __syncthreads();
#pragma unroll
        for (int st = 32; st > 0; st >>= 1) {
            if (n < st) {
                float dv = sd[n + st]; int iv = si[n + st];
                if (dv > sd[n] || (dv == sd[n] && iv < si[n])) { sd[n] = dv; si[n] = iv; }
            }
            __syncthreads();
        }
        farthest = si[0];
        __syncthreads();
    }
}

// ---------------- K2: fused sparse gather + weight transpose ----
__global__ void prep_kernel(const float* __restrict__ sp, const float* __restrict__ w,
                            float* __restrict__ sparse_out) {
    int blk = blockIdx.x;
    int tid = threadIdx.x;
    if (blk < 2048) {
        int gid = blk * 256 + tid;               // BS*SP_EMB*N_HALF = 524288
        int s = gid & 31;
        int e = (gid >> 5) & 255;
        int b = gid >> 13;
        int sid = g_fps_idx[b * N_HALF + s];
        sparse_out[gid] = sp[((size_t)b * SP_EMB + e) * N_STK + sid];
    } else {
        int idx = (blk - 2048) * 256 + tid;      // C_IN*C_OUT*4 = 131072
        int k = idx & 3;
        int o = (idx >> 2) & 255;
        int i = idx >> 10;
        g_wt[idx] = (k < 3) ? w[o * (C_IN * 3) + i * 3 + k] : 0.f;
    }
}

// ---------------- K3: gathered strided conv ---------------------
// block = (stroke s, batch b); 128 threads; thread t owns channels t, t+128.
// y[p'] = w0*v[p'-1] + w1*u[p'] + w2*v[p']  summed over i
//   u[j]=d[2j] (even taps), v[j]=d[2j+1] (odd), sw[m]=v[m-1], sw[0]=0.
// All three operands live in smem, read as aligned ulonglong2 (no per-i ALU).
#define ROWP 36   // padded row stride in floats
#define CSTEP(j, Uv, Vv, Sv)              \
    a0[j] = fma2(Sv, WA0, a0[j]);         \
    a0[j] = fma2(Uv, WA1, a0[j]);         \
    a0[j] = fma2(Vv, WA2, a0[j]);         \
    a1[j] = fma2(Sv, WB0, a1[j]);         \
    a1[j] = fma2(Uv, WB1, a1[j]);         \
    a1[j] = fma2(Vv, WB2, a1[j]);

__global__ __launch_bounds__(128, 3) void conv_kernel(const float* __restrict__ dense,
                                                      const float* __restrict__ bias) {
    __shared__ __align__(16) float sbuf[3 * C_IN * ROWP];   // 55.3 KB
    float* su = sbuf;
    float* sv = sbuf + C_IN * ROWP;
    float* sw = sbuf + 2 * C_IN * ROWP;

    int s = blockIdx.x;
    int b = blockIdx.y;
    int t = threadIdx.x;

    int sid = g_fps_idx[b * N_HALF + s];
    const float* src = dense + (size_t)b * C_IN * (N_STK * N_PNT) + sid * N_PNT;

    // fill: thread t loads channel row t (64 floats), builds u / v / shifted-v
    {
        const float4* r = (const float4*)(src + (size_t)t * (N_STK * N_PNT));
        float* pu = su + t * ROWP;
        float* pv = sv + t * ROWP;
        float* pw = sw + t * ROWP;
        pw[0] = 0.f;
#pragma unroll
        for (int q = 0; q < 16; q++) {
            float4 x = r[q];
            pu[2 * q]     = x.x;    // u[2q]   = d[4q]
            pu[2 * q + 1] = x.z;    // u[2q+1] = d[4q+2]
            pv[2 * q]     = x.y;    // v[2q]   = d[4q+1]
            pv[2 * q + 1] = x.w;    // v[2q+1] = d[4q+3]
            pw[2 * q + 1] = x.y;    // sw[2q+1] = v[2q]
            pw[2 * q + 2] = x.w;    // sw[2q+2] = v[2q+1]  (q=15 lands in pad)
        }
    }
    __syncthreads();

    int o = t;
    unsigned long long a0[16], a1[16];
#pragma unroll
    for (int j = 0; j < 16; j++) { a0[j] = 0ULL; a1[j] = 0ULL; }

    const float4* wt4 = (const float4*)g_wt;
    for (int i = 0; i < C_IN; i++) {
        float4 wA = wt4[i * C_OUT + o];          // channel o taps (coalesced)
        float4 wB = wt4[i * C_OUT + o + 128];    // channel o+128 taps
        unsigned long long WA0 = pack2(wA.x, wA.x);
        unsigned long long WA1 = pack2(wA.y, wA.y);
        unsigned long long WA2 = pack2(wA.z, wA.z);
        unsigned long long WB0 = pack2(wB.x, wB.x);
        unsigned long long WB1 = pack2(wB.y, wB.y);
        unsigned long long WB2 = pack2(wB.z, wB.z);
        const float* ru = su + i * ROWP;
        const float* rv = sv + i * ROWP;
        const float* rw = sw + i * ROWP;
#pragma unroll
        for (int c = 0; c < 4; c++) {
            ulonglong2 Ua = *(const ulonglong2*)(ru + 8 * c);
            ulonglong2 Va = *(const ulonglong2*)(rv + 8 * c);
            ulonglong2 Sa = *(const ulonglong2*)(rw + 8 * c);
            ulonglong2 Ub = *(const ulonglong2*)(ru + 8 * c + 4);
            ulonglong2 Vb = *(const ulonglong2*)(rv + 8 * c + 4);
            ulonglong2 Sb = *(const ulonglong2*)(rw + 8 * c + 4);
            CSTEP(4 * c + 0, Ua.x, Va.x, Sa.x)
            CSTEP(4 * c + 1, Ua.y, Va.y, Sa.y)
            CSTEP(4 * c + 2, Ub.x, Vb.x, Sb.x)
            CSTEP(4 * c + 3, Ub.y, Vb.y, Sb.y)
        }
    }
    __syncthreads();

    // epilogue: bias + per-channel BN partials; stage via smem (stride 33)
    float bv0 = bias[o], bv1 = bias[o + 128];
    float* sy = sbuf;   // 256*33 = 8448 floats <= 13824 available
    float s0 = 0.f, q0 = 0.f, s1 = 0.f, q1 = 0.f;
#pragma unroll
    for (int j = 0; j < 16; j++) {
        float y0, y1; unpack2(a0[j], y0, y1);
        y0 += bv0; y1 += bv0;
        sy[o * 33 + 2 * j]     = y0;
        sy[o * 33 + 2 * j + 1] = y1;
        s0 += y0 + y1;
        q0 = fmaf(y0, y0, q0); q0 = fmaf(y1, y1, q0);

        float z0, z1; unpack2(a1[j], z0, z1);
        z0 += bv1; z1 += bv1;
        sy[(o + 128) * 33 + 2 * j]     = z0;
        sy[(o + 128) * 33 + 2 * j + 1] = z1;
        s1 += z0 + z1;
        q1 = fmaf(z0, z0, q1); q1 = fmaf(z1, z1, q1);
    }
    int k = b * N_HALF + s;
    g_ps[(size_t)k * C_OUT + o]       = make_float2(s0, q0);
    g_ps[(size_t)k * C_OUT + o + 128] = make_float2(s1, q1);
    __syncthreads();

    float* dst = g_y + (size_t)b * C_OUT * 1024 + s * 32;
    for (int e = t; e < C_OUT * 32; e += 128) {
        int o2 = e >> 5, p = e & 31;
        dst[(size_t)o2 * 1024 + p] = sy[o2 * 33 + p];
    }
}

// ---------------- K4: BN finish (reduce partials) ---------------
__global__ void bn_finish(const float* __restrict__ gamma, const float* __restrict__ beta) {
    int o = blockIdx.x;
    int t = threadIdx.x;  // 256
    float S = 0.f, Q = 0.f;
    for (int k = t; k < NBLK; k += 256) {
        float2 p = g_ps[(size_t)k * C_OUT + o];
        S += p.x; Q += p.y;
    }
    __shared__ float rs[256], rq[256];
    rs[t] = S; rq[t] = Q;
    __syncthreads();
    for (int st = 128; st > 0; st >>= 1) {
        if (t < st) { rs[t] += rs[t + st]; rq[t] += rq[t + st]; }
        __syncthreads();
    }
    if (t == 0) {
        const float inv_n = 1.f / 65536.f;
        float mean = rs[0] * inv_n;
        float var  = rq[0] * inv_n - mean * mean;
        float r    = rsqrtf(var + 1e-5f);
        float sc   = gamma[o] * r;
        g_scale[o] = sc;
        g_shift[o] = beta[o] - mean * sc;
    }
}

// ---------------- K5: normalize + GELU --------------------------
__device__ __forceinline__ float gelu_f(float x) {
    float z = 0.7978845608028654f * fmaf(0.044715f * x, x * x, x);
    float e = __expf(2.f * z);
    float th = 1.f - __fdividef(2.f, e + 1.f);
    return 0.5f * x * (1.f + th);
}

__global__ void bn_gelu(float* __restrict__ out) {
    int i = blockIdx.x * blockDim.x + threadIdx.x;
    if (i < (BS * C_OUT * 1024) / 4) {
        float4 v = ((const float4*)g_y)[i];
        int o = (i >> 8) & 255;
        float sc = g_scale[o], sh = g_shift[o];
        v.x = gelu_f(fmaf(v.x, sc, sh));
        v.y = gelu_f(fmaf(v.y, sc, sh));
        v.z = gelu_f(fmaf(v.z, sc, sh));
        v.w = gelu_f(fmaf(v.w, sc, sh));
        ((float4*)out)[i] = v;
    }
}

// ---------------- launch ----------------------------------------
extern "C" void kernel_launch(void* const* d_in, const int* in_sizes, int n_in,
                              void* d_out, int out_size) {
    const float* sparse_fea = (const float*)d_in[0];   // [64,256,64]
    const float* dense_fea  = (const float*)d_in[1];   // [64,128,4096]
    const float* stk_coor   = (const float*)d_in[2];   // [64,64,32]
    const float* conv_w     = (const float*)d_in[3];   // [256,128,1,3]
    const float* conv_b     = (const float*)d_in[4];   // [256]
    const float* bn_gamma   = (const float*)d_in[5];   // [256]
    const float* bn_beta    = (const float*)d_in[6];   // [256]

    float* out = (float*)d_out;
    float* sparse_out = out;                            // 524288
    float* dense_out  = out + 524288;                   // 16777216
    float* coor_out   = out + 524288 + 16777216;        // 65536

    fps_kernel<<<BS, N_STK>>>(stk_coor, coor_out);
    prep_kernel<<<2048 + 512, 256>>>(sparse_fea, conv_w, sparse_out);
    conv_kernel<<<dim3(N_HALF, BS), 128>>>(dense_fea, conv_b);
    bn_finish<<<C_OUT, 256>>>(bn_gamma, bn_beta);
    bn_gelu<<<(BS * C_OUT * 1024 / 4 + 255) / 256, 256>>>(dense_out);
}

// round 9
// speedup vs baseline: 1.8107x; 1.3623x over previous
#include <cuda_runtime.h>
#include <cuda_bf16.h>
#include <cstdint>

// ---------------------------------------------------------------------------
// DownSample: FPS(64->32) + gathers + conv(1x3,s=2,p=1) 128->256 as a
// bf16-split mma.sync GEMM (HMMA) + BatchNorm(batch stats) + tanh-GELU.
//
// conv as GEMM: D[o, n] = sum_k W[o,k] X[n,k],  k = tap*128 + i  (K=384)
//   tap0 row = v[p'-1] (shifted), tap1 = u[p'] = d[2p'], tap2 = v[p'] = d[2p'+1]
// bf16 3-term split: W = Wh + Wl, X = Xh + Xl;  D ~= Wh*Xh + Wh*Xl + Wl*Xh.
//
// Output layout in d_out (float32):
//   [0        , 524288)    sparse_out      [64,256,32]
//   [524288   , 17301504)  dense_out       [64,256,1024]
//   [17301504 , 17367040)  stk_coor_sampled[64,32,32]
// ---------------------------------------------------------------------------

#define N_STK    64
#define N_HALF   32
#define N_PNT    64
#define COOR_EMB 32
#define BS       64
#define C_IN     128
#define C_OUT    256
#define SP_EMB   256
#define NBLK     1024        // conv CTAs = 64 b x 16 stroke-pairs
#define KSTEPS   24          // K=384 / 16

// dynamic smem (bytes): B data 2x48KB, A weights 2x16KB double buffer
#define SB_B     0           // [h][384 k-rows][128 B] xor-swizzled
#define SB_A     98304       // 2 bufs x 16384 (16 KB = one kstep, both h)
#define SMEM_TOT 131072

__device__ __align__(16) int            g_fps_idx[BS * N_HALF];
__device__ __align__(16) unsigned short g_wA[KSTEPS * 8192];           // ldmatrix-tiled bf16 weights
__device__ __align__(16) float          g_y[(size_t)BS * C_OUT * 1024]; // conv out (64 MB)
__device__ __align__(16) float2         g_ps[NBLK * C_OUT];             // per-CTA (sum, sumsq)
__device__ __align__(16) float          g_scale[C_OUT];
__device__ __align__(16) float          g_shift[C_OUT];

// ---------------- PTX helpers (all plain compute_103-legal) ------
__device__ __forceinline__ uint32_t smem_u32(const void* p) {
    uint32_t a;
    asm("{ .reg .u64 t; cvta.to.shared.u64 t, %1; cvt.u32.u64 %0, t; }" : "=r"(a) : "l"(p));
    return a;
}
#define CP_ASYNC16(dst, src) \
    asm volatile("cp.async.ca.shared.global [%0], [%1], 16;" :: "r"(dst), "l"(src))
#define CP_COMMIT() asm volatile("cp.async.commit_group;" ::: "memory")
#define CP_WAIT1()  asm volatile("cp.async.wait_group 1;" ::: "memory")
#define CP_WAIT0()  asm volatile("cp.async.wait_group 0;" ::: "memory")
#define LDX4(r, a) \
    asm volatile("ldmatrix.sync.aligned.m8n8.x4.shared.b16 {%0,%1,%2,%3}, [%4];" \
        : "=r"((r)[0]), "=r"((r)[1]), "=r"((r)[2]), "=r"((r)[3]) : "r"(a))
#define LDX4T(r, a) \
    asm volatile("ldmatrix.sync.aligned.m8n8.x4.trans.shared.b16 {%0,%1,%2,%3}, [%4];" \
        : "=r"((r)[0]), "=r"((r)[1]), "=r"((r)[2]), "=r"((r)[3]) : "r"(a))
#define MMA(d, a, b0, b1) \
    asm volatile("mma.sync.aligned.m16n8k16.row.col.f32.bf16.bf16.f32 " \
        "{%0,%1,%2,%3},{%4,%5,%6,%7},{%8,%9},{%0,%1,%2,%3};" \
        : "+f"((d)[0]), "+f"((d)[1]), "+f"((d)[2]), "+f"((d)[3]) \
        : "r"((a)[0]), "r"((a)[1]), "r"((a)[2]), "r"((a)[3]), "r"(b0), "r"(b1))

__device__ __forceinline__ unsigned short f2bh(float x) {
    __nv_bfloat16 h = __float2bfloat16_rn(x);
    return __bfloat16_as_ushort(h);
}
__device__ __forceinline__ float bh2f(unsigned short u) {
    return __bfloat162float(__ushort_as_bfloat16(u));
}

// ---------------- K1: farthest point sampling -------------------
__global__ void fps_kernel(const float* __restrict__ coor, float* __restrict__ coor_out) {
    int b = blockIdx.x;
    int n = threadIdx.x;

    float p[COOR_EMB];
    const float4* src = (const float4*)(coor + ((size_t)b * N_STK + n) * COOR_EMB);
#pragma unroll
    for (int q = 0; q < COOR_EMB / 4; q++) {
        float4 v = src[q];
        p[4 * q + 0] = v.x; p[4 * q + 1] = v.y; p[4 * q + 2] = v.z; p[4 * q + 3] = v.w;
    }

    __shared__ __align__(16) float cen[COOR_EMB];
    __shared__ float sd[N_STK];
    __shared__ int   si[N_STK];

    float dist = 1e10f;
    int farthest = 0;

    for (int it = 0; it < N_HALF; it++) {
        if (n == 0) g_fps_idx[b * N_HALF + it] = farthest;
        if (n == farthest) {
            float* co = coor_out + ((size_t)b * N_HALF + it) * COOR_EMB;
#pragma unroll
            for (int c = 0; c < COOR_EMB; c++) { cen[c] = p[c]; co[c] = p[c]; }
        }
        __syncthreads();

        float d = 0.f;
#pragma unroll
        for (int c = 0; c < COOR_EMB; c++) {
            float df = p[c] - cen[c];
            d = fmaf(df, df, d);
        }
        dist = fminf(dist, d);

        sd[n] = dist; si[n] = n;
        __syncthreads();
#pragma unroll
        for (int st = 32; st > 0; st >>= 1) {
            if (n < st) {
                float dv = sd[n + st]; int iv = si[n + st];
                if (dv > sd[n] || (dv == sd[n] && iv < si[n])) { sd[n] = dv; si[n] = iv; }
            }
            __syncthreads();
        }
        farthest = si[0];
        __syncthreads();
    }
}

// ---------------- K2: sparse gather + ldmatrix-tiled weight split ----
// A layout: elem idx = ((((ks*2 + h)*16 + MT)*4 + mat)*8 + row)*8 + col
//   m = MT*16 + (mat&1)*8 + row ; k = ks*16 + (mat>>1)*8 + col
//   tap = k>>7 ; i = k&127 ; h=0 -> bf16 hi, h=1 -> residual lo
__global__ void prep_kernel(const float* __restrict__ sp, const float* __restrict__ w,
                            float* __restrict__ sparse_out) {
    int blk = blockIdx.x;
    int tid = threadIdx.x;
    if (blk < 2048) {
        int gid = blk * 256 + tid;               // 524288 sparse elems
        int s = gid & 31;
        int e = (gid >> 5) & 255;
        int b = gid >> 13;
        int sid = g_fps_idx[b * N_HALF + s];
        sparse_out[gid] = sp[((size_t)b * SP_EMB + e) * N_STK + sid];
    } else {
        int idx = (blk - 2048) * 256 + tid;      // 196608 weight elems
        int col = idx & 7;
        int row = (idx >> 3) & 7;
        int mat = (idx >> 6) & 3;
        int MT  = (idx >> 8) & 15;
        int h   = (idx >> 12) & 1;
        int ks  = idx >> 13;
        int m = MT * 16 + (mat & 1) * 8 + row;
        int k = ks * 16 + (mat >> 1) * 8 + col;
        int tap = k >> 7, i = k & 127;
        float wv = w[m * (C_IN * 3) + i * 3 + tap];
        unsigned short wh = f2bh(wv);
        g_wA[idx] = h ? f2bh(wv - bh2f(wh)) : wh;
    }
}

// ---------------- K3: conv GEMM via mma.sync bf16 ----------------
// CTA = (b, stroke-pair): M=256 (8 warps x m32), N=64, K=384.
__global__ __launch_bounds__(256, 1)
void conv_mma_kernel(const float* __restrict__ dense, const float* __restrict__ bias) {
    extern __shared__ __align__(16) unsigned char dsm[];
    int tid = threadIdx.x, lane = tid & 31, w = tid >> 5;
    int cta = blockIdx.x;
    int b = cta >> 4, sp = cta & 15;

    uint32_t sbA = smem_u32(dsm + SB_A);
    uint32_t sbB = smem_u32(dsm + SB_B);
    const char* gA = (const char*)g_wA;

    // prologue: stream A kstep 0 into buf 0
    {
        uint32_t dst = sbA + tid * 64;
        const char* src = gA + tid * 64;
#pragma unroll
        for (int q = 0; q < 4; q++) CP_ASYNC16(dst + q * 16, src + q * 16);
        CP_COMMIT();
    }

    // ---- build B (data) rows: k = tap*128 + i, 128 B/row, xor swizzle ----
    {
        int i = tid & 127, g = tid >> 7;
        int s = sp * 2 + g;
        int sid = g_fps_idx[b * N_HALF + s];
        const float4* r4 = (const float4*)(dense + ((size_t)b * C_IN + i) * (N_STK * N_PNT)
                                           + (size_t)sid * N_PNT);
        char* Bh = (char*)dsm + SB_B;
        char* Bl = (char*)dsm + SB_B + 49152;
        uint32_t kS = i, kU = 128 + i, kV = 256 + i;
        uint32_t swS = (kS & 7) << 4, swU = (kU & 7) << 4, swV = (kV & 7) << 4;
        uint32_t ph = 0, pl = 0;     // prev v (left pad = 0)
#pragma unroll
        for (int q = 0; q < 16; q++) {
            float4 x = r4[q];
            unsigned short u0h = f2bh(x.x), v0h = f2bh(x.y);
            unsigned short u1h = f2bh(x.z), v1h = f2bh(x.w);
            unsigned short u0l = f2bh(x.x - bh2f(u0h));
            unsigned short v0l = f2bh(x.y - bh2f(v0h));
            unsigned short u1l = f2bh(x.z - bh2f(u1h));
            unsigned short v1l = f2bh(x.w - bh2f(v1h));
            uint32_t n2 = (uint32_t)(g * 32 + 2 * q) * 2;   // byte col
            *(uint32_t*)(Bh + kU * 128 + (n2 ^ swU)) = (uint32_t)u0h | ((uint32_t)u1h << 16);
            *(uint32_t*)(Bl + kU * 128 + (n2 ^ swU)) = (uint32_t)u0l | ((uint32_t)u1l << 16);
            *(uint32_t*)(Bh + kV * 128 + (n2 ^ swV)) = (uint32_t)v0h | ((uint32_t)v1h << 16);
            *(uint32_t*)(Bl + kV * 128 + (n2 ^ swV)) = (uint32_t)v0l | ((uint32_t)v1l << 16);
            *(uint32_t*)(Bh + kS * 128 + (n2 ^ swS)) = ph | ((uint32_t)v0h << 16);
            *(uint32_t*)(Bl + kS * 128 + (n2 ^ swS)) = pl | ((uint32_t)v0l << 16);
            ph = v1h; pl = v1l;
        }
    }

    float acc[2][8][4];
#pragma unroll
    for (int mt = 0; mt < 2; mt++)
#pragma unroll
        for (int nt = 0; nt < 8; nt++)
#pragma unroll
            for (int e = 0; e < 4; e++) acc[mt][nt][e] = 0.f;

    // B ldmatrix.trans base addressing for this lane
    int j = lane >> 3;                       // matrix index 0..3
    int krow = (j & 1) * 8 + (lane & 7);     // k within kstep
    int ncol = (j >> 1) * 8;                 // n offset within n-pair group

    for (int ks = 0; ks < KSTEPS; ks++) {
        int buf = ks & 1;
        if (ks < KSTEPS - 1) {
            uint32_t dst = sbA + ((ks + 1) & 1) * 16384 + tid * 64;
            const char* src = gA + (size_t)(ks + 1) * 16384 + tid * 64;
#pragma unroll
            for (int q = 0; q < 4; q++) CP_ASYNC16(dst + q * 16, src + q * 16);
            CP_COMMIT();
            CP_WAIT1();
        } else {
            CP_WAIT0();
        }
        __syncthreads();

        // A fragments (hi+lo, 2 m-tiles)
        uint32_t aB = sbA + buf * 16384 + (uint32_t)(lane >> 3) * 128 + (uint32_t)(lane & 7) * 16;
        uint32_t Ah0[4], Ah1[4], Al0[4], Al1[4];
        LDX4(Ah0, aB + (uint32_t)(w * 2 + 0) * 512);
        LDX4(Ah1, aB + (uint32_t)(w * 2 + 1) * 512);
        LDX4(Al0, aB + 8192 + (uint32_t)(w * 2 + 0) * 512);
        LDX4(Al1, aB + 8192 + (uint32_t)(w * 2 + 1) * 512);

        int kk = ks * 16 + krow;
        uint32_t rowb = (uint32_t)kk * 128;
        uint32_t swz = (uint32_t)(kk & 7) << 4;

        uint32_t Bf[4][4];
        // ---- X hi: Wh*Xh + Wl*Xh ----
#pragma unroll
        for (int np = 0; np < 4; np++) {
            uint32_t nb = (uint32_t)((np * 16 + ncol) * 2);
            LDX4T(Bf[np], sbB + rowb + (nb ^ swz));
        }
#pragma unroll
        for (int np = 0; np < 4; np++) {
            MMA(acc[0][np * 2],     Ah0, Bf[np][0], Bf[np][1]);
            MMA(acc[0][np * 2 + 1], Ah0, Bf[np][2], Bf[np][3]);
            MMA(acc[1][np * 2],     Ah1, Bf[np][0], Bf[np][1]);
            MMA(acc[1][np * 2 + 1], Ah1, Bf[np][2], Bf[np][3]);
            MMA(acc[0][np * 2],     Al0, Bf[np][0], Bf[np][1]);
            MMA(acc[0][np * 2 + 1], Al0, Bf[np][2], Bf[np][3]);
            MMA(acc[1][np * 2],     Al1, Bf[np][0], Bf[np][1]);
            MMA(acc[1][np * 2 + 1], Al1, Bf[np][2], Bf[np][3]);
        }
        // ---- X lo: Wh*Xl ----
#pragma unroll
        for (int np = 0; np < 4; np++) {
            uint32_t nb = (uint32_t)((np * 16 + ncol) * 2);
            LDX4T(Bf[np], sbB + 49152 + rowb + (nb ^ swz));
        }
#pragma unroll
        for (int np = 0; np < 4; np++) {
            MMA(acc[0][np * 2],     Ah0, Bf[np][0], Bf[np][1]);
            MMA(acc[0][np * 2 + 1], Ah0, Bf[np][2], Bf[np][3]);
            MMA(acc[1][np * 2],     Ah1, Bf[np][0], Bf[np][1]);
            MMA(acc[1][np * 2 + 1], Ah1, Bf[np][2], Bf[np][3]);
        }
        __syncthreads();
    }

    // ---- epilogue: stage D in smem, then bias + BN partials + store ----
    float* sy = (float*)dsm;    // 256 rows x stride 66 = 67.6 KB
    int r = lane >> 2, c2 = (lane & 3) * 2;
#pragma unroll
    for (int mt = 0; mt < 2; mt++) {
        int m = w * 32 + mt * 16 + r;
#pragma unroll
        for (int nt = 0; nt < 8; nt++) {
            int n = nt * 8 + c2;
            *(float2*)(sy + m * 66 + n)       = make_float2(acc[mt][nt][0], acc[mt][nt][1]);
            *(float2*)(sy + (m + 8) * 66 + n) = make_float2(acc[mt][nt][2], acc[mt][nt][3]);
        }
    }
    __syncthreads();

    {
        int o = tid;
        float bv = bias[o];
        float S = 0.f, Q = 0.f;
        float* row = sy + o * 66;
        float* dst = g_y + ((size_t)b * C_OUT + o) * 1024 + sp * 64;
#pragma unroll
        for (int n = 0; n < 64; n++) {
            float y = row[n] + bv;
            S += y; Q = fmaf(y, y, Q);
            dst[n] = y;    // positions (sp*2 + n/32)*32 + n%32 == sp*64 + n
        }
        g_ps[(size_t)cta * C_OUT + o] = make_float2(S, Q);
    }
}

// ---------------- K4: BN finish ---------------------------------
__global__ void bn_finish(const float* __restrict__ gamma, const float* __restrict__ beta) {
    int o = blockIdx.x;
    int t = threadIdx.x;  // 256
    float S = 0.f, Q = 0.f;
    for (int k = t; k < NBLK; k += 256) {
        float2 p = g_ps[(size_t)k * C_OUT + o];
        S += p.x; Q += p.y;
    }
    __shared__ float rs[256], rq[256];
    rs[t] = S; rq[t] = Q;
    __syncthreads();
    for (int st = 128; st > 0; st >>= 1) {
        if (t < st) { rs[t] += rs[t + st]; rq[t] += rq[t + st]; }
        __syncthreads();
    }
    if (t == 0) {
        const float inv_n = 1.f / 65536.f;
        float mean = rs[0] * inv_n;
        float var  = rq[0] * inv_n - mean * mean;
        float r    = rsqrtf(var + 1e-5f);
        float sc   = gamma[o] * r;
        g_scale[o] = sc;
        g_shift[o] = beta[o] - mean * sc;
    }
}

// ---------------- K5: normalize + GELU --------------------------
__device__ __forceinline__ float gelu_f(float x) {
    float z = 0.7978845608028654f * fmaf(0.044715f * x, x * x, x);
    float e = __expf(2.f * z);
    float th = 1.f - __fdividef(2.f, e + 1.f);
    return 0.5f * x * (1.f + th);
}

__global__ void bn_gelu(float* __restrict__ out) {
    int i = blockIdx.x * blockDim.x + threadIdx.x;
    if (i < (BS * C_OUT * 1024) / 4) {
        float4 v = ((const float4*)g_y)[i];
        int o = (i >> 8) & 255;
        float sc = g_scale[o], sh = g_shift[o];
        v.x = gelu_f(fmaf(v.x, sc, sh));
        v.y = gelu_f(fmaf(v.y, sc, sh));
        v.z = gelu_f(fmaf(v.z, sc, sh));
        v.w = gelu_f(fmaf(v.w, sc, sh));
        ((float4*)out)[i] = v;
    }
}

// ---------------- launch ----------------------------------------
extern "C" void kernel_launch(void* const* d_in, const int* in_sizes, int n_in,
                              void* d_out, int out_size) {
    const float* sparse_fea = (const float*)d_in[0];   // [64,256,64]
    const float* dense_fea  = (const float*)d_in[1];   // [64,128,4096]
    const float* stk_coor   = (const float*)d_in[2];   // [64,64,32]
    const float* conv_w     = (const float*)d_in[3];   // [256,128,1,3]
    const float* conv_b     = (const float*)d_in[4];   // [256]
    const float* bn_gamma   = (const float*)d_in[5];   // [256]
    const float* bn_beta    = (const float*)d_in[6];   // [256]

    float* out = (float*)d_out;
    float* sparse_out = out;                            // 524288
    float* dense_out  = out + 524288;                   // 16777216
    float* coor_out   = out + 524288 + 16777216;        // 65536

    cudaFuncSetAttribute(conv_mma_kernel, cudaFuncAttributeMaxDynamicSharedMemorySize, SMEM_TOT);

    fps_kernel<<<BS, N_STK>>>(stk_coor, coor_out);
    prep_kernel<<<2048 + 768, 256>>>(sparse_fea, conv_w, sparse_out);
    conv_mma_kernel<<<NBLK, 256, SMEM_TOT>>>(dense_fea, conv_b);
    bn_finish<<<C_OUT, 256>>>(bn_gamma, bn_beta);
    bn_gelu<<<(BS * C_OUT * 1024 / 4 + 255) / 256, 256>>>(dense_out);
}

// round 11
// speedup vs baseline: 1.9159x; 1.0581x over previous
#include <cuda_runtime.h>
#include <cuda_bf16.h>
#include <cstdint>

// ---------------------------------------------------------------------------
// DownSample: FPS(64->32) + gathers + conv(1x3,s=2,p=1) 128->256 as a
// bf16-split mma.sync GEMM (HMMA) + BatchNorm(batch stats) + tanh-GELU.
//
// conv as GEMM: D[o, n] = sum_k W[o,k] X[n,k],  k = tap*128 + i  (K=384)
// bf16 3-term split: W = Wh + Wl, X = Xh + Xl;  D ~= Wh*Xh + Wh*Xl + Wl*Xh.
//
// Output layout in d_out (float32):
//   [0        , 524288)    sparse_out      [64,256,32]
//   [524288   , 17301504)  dense_out       [64,256,1024]
//   [17301504 , 17367040)  stk_coor_sampled[64,32,32]
// ---------------------------------------------------------------------------

#define N_STK    64
#define N_HALF   32
#define N_PNT    64
#define COOR_EMB 32
#define BS       64
#define C_IN     128
#define C_OUT    256
#define SP_EMB   256
#define NBLK     1024        // conv CTAs = 64 b x 16 stroke-pairs
#define KSTEPS   24          // K=384 / 16

// dynamic smem (bytes): B data 96KB, A weights 4x16KB ring
#define SB_B     0           // [h][384 k-rows][128 B] xor-swizzled
#define SB_A     98304       // 4 bufs x 16384
#define SMEM_TOT 163840

__device__ __align__(16) int            g_fps_idx[BS * N_HALF];
__device__ __align__(16) unsigned short g_wA[KSTEPS * 8192];           // ldmatrix-tiled bf16 weights
__device__ __align__(16) float          g_y[(size_t)BS * C_OUT * 1024]; // conv out (64 MB)
__device__ __align__(16) float2         g_ps[NBLK * C_OUT];             // per-CTA (sum, sumsq)
__device__ __align__(16) float          g_scale[C_OUT];
__device__ __align__(16) float          g_shift[C_OUT];

// ---------------- PTX helpers (plain compute_103-legal) ----------
__device__ __forceinline__ uint32_t smem_u32(const void* p) {
    uint32_t a;
    asm("{ .reg .u64 t; cvta.to.shared.u64 t, %1; cvt.u32.u64 %0, t; }" : "=r"(a) : "l"(p));
    return a;
}
#define CP_ASYNC16(dst, src) \
    asm volatile("cp.async.ca.shared.global [%0], [%1], 16;" :: "r"(dst), "l"(src))
#define CP_COMMIT() asm volatile("cp.async.commit_group;" ::: "memory")
#define CP_WAIT2()  asm volatile("cp.async.wait_group 2;" ::: "memory")
#define LDX4(r, a) \
    asm volatile("ldmatrix.sync.aligned.m8n8.x4.shared.b16 {%0,%1,%2,%3}, [%4];" \
        : "=r"((r)[0]), "=r"((r)[1]), "=r"((r)[2]), "=r"((r)[3]) : "r"(a))
#define LDX4T(r, a) \
    asm volatile("ldmatrix.sync.aligned.m8n8.x4.trans.shared.b16 {%0,%1,%2,%3}, [%4];" \
        : "=r"((r)[0]), "=r"((r)[1]), "=r"((r)[2]), "=r"((r)[3]) : "r"(a))
#define MMA(d, a, b0, b1) \
    asm volatile("mma.sync.aligned.m16n8k16.row.col.f32.bf16.bf16.f32 " \
        "{%0,%1,%2,%3},{%4,%5,%6,%7},{%8,%9},{%0,%1,%2,%3};" \
        : "+f"((d)[0]), "+f"((d)[1]), "+f"((d)[2]), "+f"((d)[3]) \
        : "r"((a)[0]), "r"((a)[1]), "r"((a)[2]), "r"((a)[3]), "r"(b0), "r"(b1))

__device__ __forceinline__ unsigned short f2bh(float x) {
    __nv_bfloat16 h = __float2bfloat16_rn(x);
    return __bfloat16_as_ushort(h);
}
__device__ __forceinline__ float bh2f(unsigned short u) {
    return __bfloat162float(__ushort_as_bfloat16(u));
}

// ---------------- K1: farthest point sampling -------------------
__global__ void fps_kernel(const float* __restrict__ coor, float* __restrict__ coor_out) {
    int b = blockIdx.x;
    int n = threadIdx.x;

    float p[COOR_EMB];
    const float4* src = (const float4*)(coor + ((size_t)b * N_STK + n) * COOR_EMB);
#pragma unroll
    for (int q = 0; q < COOR_EMB / 4; q++) {
        float4 v = src[q];
        p[4 * q + 0] = v.x; p[4 * q + 1] = v.y; p[4 * q + 2] = v.z; p[4 * q + 3] = v.w;
    }

    __shared__ __align__(16) float cen[COOR_EMB];
    __shared__ float sd[N_STK];
    __shared__ int   si[N_STK];

    float dist = 1e10f;
    int farthest = 0;

    for (int it = 0; it < N_HALF; it++) {
        if (n == 0) g_fps_idx[b * N_HALF + it] = farthest;
        if (n == farthest) {
            float* co = coor_out + ((size_t)b * N_HALF + it) * COOR_EMB;
#pragma unroll
            for (int c = 0; c < COOR_EMB; c++) { cen[c] = p[c]; co[c] = p[c]; }
        }
        __syncthreads();

        float d = 0.f;
#pragma unroll
        for (int c = 0; c < COOR_EMB; c++) {
            float df = p[c] - cen[c];
            d = fmaf(df, df, d);
        }
        dist = fminf(dist, d);

        sd[n] = dist; si[n] = n;
        __syncthreads();
#pragma unroll
        for (int st = 32; st > 0; st >>= 1) {
            if (n < st) {
                float dv = sd[n + st]; int iv = si[n + st];
                if (dv > sd[n] || (dv == sd[n] && iv < si[n])) { sd[n] = dv; si[n] = iv; }
            }
            __syncthreads();
        }
        farthest = si[0];
        __syncthreads();
    }
}

// ---------------- K2a: sparse gather ----------------------------
__global__ void gather_sparse(const float* __restrict__ sp, float* __restrict__ out) {
    int gid = blockIdx.x * blockDim.x + threadIdx.x;
    if (gid < BS * SP_EMB * N_HALF) {
        int s = gid & 31;
        int e = (gid >> 5) & 255;
        int b = gid >> 13;
        int sid = g_fps_idx[b * N_HALF + s];
        out[gid] = sp[((size_t)b * SP_EMB + e) * N_STK + sid];
    }
}

// ---------------- K2b: ldmatrix-tiled bf16 weight split ---------
// elem idx = ((((ks*2 + h)*16 + MT)*4 + mat)*8 + row)*8 + col
//   m = MT*16 + (mat&1)*8 + row ; k = ks*16 + (mat>>1)*8 + col
//   tap = k>>7 ; i = k&127 ; h=0 -> bf16 hi, h=1 -> residual lo
__global__ void wsplit(const float* __restrict__ w) {
    int idx = blockIdx.x * blockDim.x + threadIdx.x;
    if (idx < KSTEPS * 8192) {
        int col = idx & 7;
        int row = (idx >> 3) & 7;
        int mat = (idx >> 6) & 3;
        int MT  = (idx >> 8) & 15;
        int h   = (idx >> 12) & 1;
        int ks  = idx >> 13;
        int m = MT * 16 + (mat & 1) * 8 + row;
        int k = ks * 16 + (mat >> 1) * 8 + col;
        int tap = k >> 7, i = k & 127;
        float wv = w[m * (C_IN * 3) + i * 3 + tap];
        unsigned short wh = f2bh(wv);
        g_wA[idx] = h ? f2bh(wv - bh2f(wh)) : wh;
    }
}

// ---------------- K3: conv GEMM via mma.sync bf16 ----------------
// CTA = (b, stroke-pair): M=256 (8 warps x m32), N=64, K=384.
// A streamed through a 4-stage cp.async ring (depth-3 prefetch).
__global__ __launch_bounds__(256, 1)
void conv_mma_kernel(const float* __restrict__ dense, const float* __restrict__ bias) {
    extern __shared__ __align__(16) unsigned char dsm[];
    int tid = threadIdx.x, lane = tid & 31, w = tid >> 5;
    int cta = blockIdx.x;
    int b = cta >> 4, sp = cta & 15;

    uint32_t sbA = smem_u32(dsm + SB_A);
    uint32_t sbB = smem_u32(dsm + SB_B);
    const char* gA = (const char*)g_wA;

    // prologue: stream A ksteps 0..2 into bufs 0..2 (3 committed groups)
#pragma unroll
    for (int pk = 0; pk < 3; pk++) {
        uint32_t dst = sbA + (uint32_t)pk * 16384 + tid * 64;
        const char* src = gA + (size_t)pk * 16384 + tid * 64;
#pragma unroll
        for (int q = 0; q < 4; q++) CP_ASYNC16(dst + q * 16, src + q * 16);
        CP_COMMIT();
    }

    // ---- build B (data) rows: k = tap*128 + i, 128 B/row, xor swizzle ----
    {
        int i = tid & 127, g = tid >> 7;
        int s = sp * 2 + g;
        int sid = g_fps_idx[b * N_HALF + s];
        const float4* r4 = (const float4*)(dense + ((size_t)b * C_IN + i) * (N_STK * N_PNT)
                                           + (size_t)sid * N_PNT);
        char* Bh = (char*)dsm + SB_B;
        char* Bl = (char*)dsm + SB_B + 49152;
        uint32_t kS = i, kU = 128 + i, kV = 256 + i;
        uint32_t swS = (kS & 7) << 4, swU = (kU & 7) << 4, swV = (kV & 7) << 4;
        uint32_t ph = 0, pl = 0;     // prev v (left pad = 0)
#pragma unroll
        for (int q = 0; q < 16; q++) {
            float4 x = r4[q];
            unsigned short u0h = f2bh(x.x), v0h = f2bh(x.y);
            unsigned short u1h = f2bh(x.z), v1h = f2bh(x.w);
            unsigned short u0l = f2bh(x.x - bh2f(u0h));
            unsigned short v0l = f2bh(x.y - bh2f(v0h));
            unsigned short u1l = f2bh(x.z - bh2f(u1h));
            unsigned short v1l = f2bh(x.w - bh2f(v1h));
            uint32_t n2 = (uint32_t)(g * 32 + 2 * q) * 2;   // byte col
            *(uint32_t*)(Bh + kU * 128 + (n2 ^ swU)) = (uint32_t)u0h | ((uint32_t)u1h << 16);
            *(uint32_t*)(Bl + kU * 128 + (n2 ^ swU)) = (uint32_t)u0l | ((uint32_t)u1l << 16);
            *(uint32_t*)(Bh + kV * 128 + (n2 ^ swV)) = (uint32_t)v0h | ((uint32_t)v1h << 16);
            *(uint32_t*)(Bl + kV * 128 + (n2 ^ swV)) = (uint32_t)v0l | ((uint32_t)v1l << 16);
            *(uint32_t*)(Bh + kS * 128 + (n2 ^ swS)) = ph | ((uint32_t)v0h << 16);
            *(uint32_t*)(Bl + kS * 128 + (n2 ^ swS)) = pl | ((uint32_t)v0l << 16);
            ph = v1h; pl = v1l;
        }
    }

    float acc[2][8][4];
#pragma unroll
    for (int mt = 0; mt < 2; mt++)
#pragma unroll
        for (int nt = 0; nt < 8; nt++)
#pragma unroll
            for (int e = 0; e < 4; e++) acc[mt][nt][e] = 0.f;

    int j = lane >> 3;                       // matrix index 0..3
    int krow = (j & 1) * 8 + (lane & 7);     // k within kstep
    int ncol = (j >> 1) * 8;                 // n offset

    for (int ks = 0; ks < KSTEPS; ks++) {
        int buf = ks & 3;
        CP_WAIT2();          // pending kept at 3 → retires group ks
        __syncthreads();     // all warps past reads of buf (ks-1)&3

        // prefetch kstep ks+3 into buf (ks+3)&3; commit ALWAYS (possibly empty)
        if (ks + 3 < KSTEPS) {
            uint32_t dst = sbA + (uint32_t)((ks + 3) & 3) * 16384 + tid * 64;
            const char* src = gA + (size_t)(ks + 3) * 16384 + tid * 64;
#pragma unroll
            for (int q = 0; q < 4; q++) CP_ASYNC16(dst + q * 16, src + q * 16);
        }
        CP_COMMIT();

        // A fragments (hi+lo, 2 m-tiles)
        uint32_t aB = sbA + (uint32_t)buf * 16384 + (uint32_t)(lane >> 3) * 128
                      + (uint32_t)(lane & 7) * 16;
        uint32_t Ah0[4], Ah1[4], Al0[4], Al1[4];
        LDX4(Ah0, aB + (uint32_t)(w * 2 + 0) * 512);
        LDX4(Ah1, aB + (uint32_t)(w * 2 + 1) * 512);
        LDX4(Al0, aB + 8192 + (uint32_t)(w * 2 + 0) * 512);
        LDX4(Al1, aB + 8192 + (uint32_t)(w * 2 + 1) * 512);

        int kk = ks * 16 + krow;
        uint32_t rowb = (uint32_t)kk * 128;
        uint32_t swz = (uint32_t)(kk & 7) << 4;

        uint32_t Bf[4][4];
        // ---- X hi: Wh*Xh + Wl*Xh ----
#pragma unroll
        for (int np = 0; np < 4; np++) {
            uint32_t nb = (uint32_t)((np * 16 + ncol) * 2);
            LDX4T(Bf[np], sbB + rowb + (nb ^ swz));
        }
#pragma unroll
        for (int np = 0; np < 4; np++) {
            MMA(acc[0][np * 2],     Ah0, Bf[np][0], Bf[np][1]);
            MMA(acc[0][np * 2 + 1], Ah0, Bf[np][2], Bf[np][3]);
            MMA(acc[1][np * 2],     Ah1, Bf[np][0], Bf[np][1]);
            MMA(acc[1][np * 2 + 1], Ah1, Bf[np][2], Bf[np][3]);
            MMA(acc[0][np * 2],     Al0, Bf[np][0], Bf[np][1]);
            MMA(acc[0][np * 2 + 1], Al0, Bf[np][2], Bf[np][3]);
            MMA(acc[1][np * 2],     Al1, Bf[np][0], Bf[np][1]);
            MMA(acc[1][np * 2 + 1], Al1, Bf[np][2], Bf[np][3]);
        }
        // ---- X lo: Wh*Xl ----
#pragma unroll
        for (int np = 0; np < 4; np++) {
            uint32_t nb = (uint32_t)((np * 16 + ncol) * 2);
            LDX4T(Bf[np], sbB + 49152 + rowb + (nb ^ swz));
        }
#pragma unroll
        for (int np = 0; np < 4; np++) {
            MMA(acc[0][np * 2],     Ah0, Bf[np][0], Bf[np][1]);
            MMA(acc[0][np * 2 + 1], Ah0, Bf[np][2], Bf[np][3]);
            MMA(acc[1][np * 2],     Ah1, Bf[np][0], Bf[np][1]);
            MMA(acc[1][np * 2 + 1], Ah1, Bf[np][2], Bf[np][3]);
        }
    }
    __syncthreads();

    // ---- epilogue: stage D in smem, then bias + BN partials + store ----
    float* sy = (float*)dsm;    // 256 rows x stride 66 = 67.6 KB
    int r = lane >> 2, c2 = (lane & 3) * 2;
#pragma unroll
    for (int mt = 0; mt < 2; mt++) {
        int m = w * 32 + mt * 16 + r;
#pragma unroll
        for (int nt = 0; nt < 8; nt++) {
            int n = nt * 8 + c2;
            *(float2*)(sy + m * 66 + n)       = make_float2(acc[mt][nt][0], acc[mt][nt][1]);
            *(float2*)(sy + (m + 8) * 66 + n) = make_float2(acc[mt][nt][2], acc[mt][nt][3]);
        }
    }
    __syncthreads();

    {
        int o = tid;
        float bv = bias[o];
        float S = 0.f, Q = 0.f;
        float* row = sy + o * 66;
        float* dst = g_y + ((size_t)b * C_OUT + o) * 1024 + sp * 64;
#pragma unroll
        for (int n = 0; n < 64; n++) {
            float y = row[n] + bv;
            S += y; Q = fmaf(y, y, Q);
            dst[n] = y;
        }
        g_ps[(size_t)cta * C_OUT + o] = make_float2(S, Q);
    }
}

// ---------------- K4: BN finish ---------------------------------
__global__ void bn_finish(const float* __restrict__ gamma, const float* __restrict__ beta) {
    int o = blockIdx.x;
    int t = threadIdx.x;  // 256
    float S = 0.f, Q = 0.f;
    for (int k = t; k < NBLK; k += 256) {
        float2 p = g_ps[(size_t)k * C_OUT + o];
        S += p.x; Q += p.y;
    }
    __shared__ float rs[256], rq[256];
    rs[t] = S; rq[t] = Q;
    __syncthreads();
    for (int st = 128; st > 0; st >>= 1) {
        if (t < st) { rs[t] += rs[t + st]; rq[t] += rq[t + st]; }
        __syncthreads();
    }
    if (t == 0) {
        const float inv_n = 1.f / 65536.f;
        float mean = rs[0] * inv_n;
        float var  = rq[0] * inv_n - mean * mean;
        float r    = rsqrtf(var + 1e-5f);
        float sc   = gamma[o] * r;
        g_scale[o] = sc;
        g_shift[o] = beta[o] - mean * sc;
    }
}

// ---------------- K5: normalize + GELU --------------------------
__device__ __forceinline__ float gelu_f(float x) {
    float z = 0.7978845608028654f * fmaf(0.044715f * x, x * x, x);
    float e = __expf(2.f * z);
    float th = 1.f - __fdividef(2.f, e + 1.f);
    return 0.5f * x * (1.f + th);
}

__global__ void bn_gelu(float* __restrict__ out) {
    int i = blockIdx.x * blockDim.x + threadIdx.x;
    if (i < (BS * C_OUT * 1024) / 4) {
        float4 v = ((const float4*)g_y)[i];
        int o = (i >> 8) & 255;
        float sc = g_scale[o], sh = g_shift[o];
        v.x = gelu_f(fmaf(v.x, sc, sh));
        v.y = gelu_f(fmaf(v.y, sc, sh));
        v.z = gelu_f(fmaf(v.z, sc, sh));
        v.w = gelu_f(fmaf(v.w, sc, sh));
        ((float4*)out)[i] = v;
    }
}

// ---------------- launch ----------------------------------------
extern "C" void kernel_launch(void* const* d_in, const int* in_sizes, int n_in,
                              void* d_out, int out_size) {
    const float* sparse_fea = (const float*)d_in[0];   // [64,256,64]
    const float* dense_fea  = (const float*)d_in[1];   // [64,128,4096]
    const float* stk_coor   = (const float*)d_in[2];   // [64,64,32]
    const float* conv_w     = (const float*)d_in[3];   // [256,128,1,3]
    const float* conv_b     = (const float*)d_in[4];   // [256]
    const float* bn_gamma   = (const float*)d_in[5];   // [256]
    const float* bn_beta    = (const float*)d_in[6];   // [256]

    float* out = (float*)d_out;
    float* sparse_out = out;                            // 524288
    float* dense_out  = out + 524288;                   // 16777216
    float* coor_out   = out + 524288 + 16777216;        // 65536

    cudaFuncSetAttribute(conv_mma_kernel, cudaFuncAttributeMaxDynamicSharedMemorySize, SMEM_TOT);

    fps_kernel<<<BS, N_STK>>>(stk_coor, coor_out);                               // 1
    gather_sparse<<<(BS * SP_EMB * N_HALF + 255) / 256, 256>>>(sparse_fea, sparse_out); // 2
    wsplit<<<(KSTEPS * 8192 + 255) / 256, 256>>>(conv_w);                         // 3
    conv_mma_kernel<<<NBLK, 256, SMEM_TOT>>>(dense_fea, conv_b);                  // 4 (profiled)
    bn_finish<<<C_OUT, 256>>>(bn_gamma, bn_beta);                                 // 5
    bn_gelu<<<(BS * C_OUT * 1024 / 4 + 255) / 256, 256>>>(dense_out);             // 6
}

// round 12
// speedup vs baseline: 2.1952x; 1.1458x over previous
#include <cuda_runtime.h>
#include <cuda_bf16.h>
#include <cstdint>

// ---------------------------------------------------------------------------
// DownSample: FPS(64->32) + gathers + conv(1x3,s=2,p=1) 128->256 as a
// bf16-split mma.sync GEMM (HMMA) + BatchNorm(batch stats) + tanh-GELU.
//
// conv as GEMM: D[o, n] = sum_k W[o,k] X[n,k],  k = tap*128 + i  (K=384)
// bf16 3-term split: W = Wh + Wl, X = Xh + Xl;  D ~= Wh*Xh + Wh*Xl + Wl*Xh.
//
// Output layout in d_out (float32):
//   [0        , 524288)    sparse_out      [64,256,32]
//   [524288   , 17301504)  dense_out       [64,256,1024]
//   [17301504 , 17367040)  stk_coor_sampled[64,32,32]
// ---------------------------------------------------------------------------

#define N_STK    64
#define N_HALF   32
#define N_PNT    64
#define COOR_EMB 32
#define BS       64
#define C_IN     128
#define C_OUT    256
#define SP_EMB   256
#define NBLK     1024        // conv CTAs = 64 b x 16 stroke-pairs
#define KSTEPS   24          // K=384 / 16

// dynamic smem (bytes): B data 96KB, A weights 4x16KB ring
#define SB_B     0           // [h][384 k-rows][128 B] xor-swizzled
#define SB_A     98304       // 4 bufs x 16384
#define SMEM_TOT 163840

__device__ __align__(16) int            g_fps_idx[BS * N_HALF];
__device__ __align__(16) unsigned short g_wA[KSTEPS * 8192];           // ldmatrix-tiled bf16 weights
__device__ __align__(16) float          g_y[(size_t)BS * C_OUT * 1024]; // conv out (64 MB)
__device__ __align__(16) float2         g_ps[NBLK * C_OUT];             // per-CTA (sum, sumsq)
__device__ __align__(16) float          g_scale[C_OUT];
__device__ __align__(16) float          g_shift[C_OUT];

// ---------------- PTX helpers (plain compute_103-legal) ----------
__device__ __forceinline__ uint32_t smem_u32(const void* p) {
    uint32_t a;
    asm("{ .reg .u64 t; cvta.to.shared.u64 t, %1; cvt.u32.u64 %0, t; }" : "=r"(a) : "l"(p));
    return a;
}
#define CP_ASYNC16(dst, src) \
    asm volatile("cp.async.ca.shared.global [%0], [%1], 16;" :: "r"(dst), "l"(src))
#define CP_COMMIT() asm volatile("cp.async.commit_group;" ::: "memory")
#define CP_WAIT2()  asm volatile("cp.async.wait_group 2;" ::: "memory")
#define LDX4(r, a) \
    asm volatile("ldmatrix.sync.aligned.m8n8.x4.shared.b16 {%0,%1,%2,%3}, [%4];" \
        : "=r"((r)[0]), "=r"((r)[1]), "=r"((r)[2]), "=r"((r)[3]) : "r"(a))
#define LDX4T(r, a) \
    asm volatile("ldmatrix.sync.aligned.m8n8.x4.trans.shared.b16 {%0,%1,%2,%3}, [%4];" \
        : "=r"((r)[0]), "=r"((r)[1]), "=r"((r)[2]), "=r"((r)[3]) : "r"(a))
#define MMA(d, a, b0, b1) \
    asm volatile("mma.sync.aligned.m16n8k16.row.col.f32.bf16.bf16.f32 " \
        "{%0,%1,%2,%3},{%4,%5,%6,%7},{%8,%9},{%0,%1,%2,%3};" \
        : "+f"((d)[0]), "+f"((d)[1]), "+f"((d)[2]), "+f"((d)[3]) \
        : "r"((a)[0]), "r"((a)[1]), "r"((a)[2]), "r"((a)[3]), "r"(b0), "r"(b1))

__device__ __forceinline__ unsigned short f2bh(float x) {
    __nv_bfloat16 h = __float2bfloat16_rn(x);
    return __bfloat16_as_ushort(h);
}
__device__ __forceinline__ float bh2f(unsigned short u) {
    return __bfloat162float(__ushort_as_bfloat16(u));
}

// ---------------- K1: farthest point sampling -------------------
__global__ void fps_kernel(const float* __restrict__ coor, float* __restrict__ coor_out) {
    int b = blockIdx.x;
    int n = threadIdx.x;

    float p[COOR_EMB];
    const float4* src = (const float4*)(coor + ((size_t)b * N_STK + n) * COOR_EMB);
#pragma unroll
    for (int q = 0; q < COOR_EMB / 4; q++) {
        float4 v = src[q];
        p[4 * q + 0] = v.x; p[4 * q + 1] = v.y; p[4 * q + 2] = v.z; p[4 * q + 3] = v.w;
    }

    __shared__ __align__(16) float cen[COOR_EMB];
    __shared__ float sd[N_STK];
    __shared__ int   si[N_STK];

    float dist = 1e10f;
    int farthest = 0;

    for (int it = 0; it < N_HALF; it++) {
        if (n == 0) g_fps_idx[b * N_HALF + it] = farthest;
        if (n == farthest) {
            float* co = coor_out + ((size_t)b * N_HALF + it) * COOR_EMB;
#pragma unroll
            for (int c = 0; c < COOR_EMB; c++) { cen[c] = p[c]; co[c] = p[c]; }
        }
        __syncthreads();

        float d = 0.f;
#pragma unroll
        for (int c = 0; c < COOR_EMB; c++) {
            float df = p[c] - cen[c];
            d = fmaf(df, df, d);
        }
        dist = fminf(dist, d);

        sd[n] = dist; si[n] = n;
        __syncthreads();
#pragma unroll
        for (int st = 32; st > 0; st >>= 1) {
            if (n < st) {
                float dv = sd[n + st]; int iv = si[n + st];
                if (dv > sd[n] || (dv == sd[n] && iv < si[n])) { sd[n] = dv; si[n] = iv; }
            }
            __syncthreads();
        }
        farthest = si[0];
        __syncthreads();
    }
}

// ---------------- K2a: sparse gather ----------------------------
__global__ void gather_sparse(const float* __restrict__ sp, float* __restrict__ out) {
    int gid = blockIdx.x * blockDim.x + threadIdx.x;
    if (gid < BS * SP_EMB * N_HALF) {
        int s = gid & 31;
        int e = (gid >> 5) & 255;
        int b = gid >> 13;
        int sid = g_fps_idx[b * N_HALF + s];
        out[gid] = sp[((size_t)b * SP_EMB + e) * N_STK + sid];
    }
}

// ---------------- K2b: ldmatrix-tiled bf16 weight split ---------
// elem idx = ((((ks*2 + h)*16 + MT)*4 + mat)*8 + row)*8 + col
//   m = MT*16 + (mat&1)*8 + row ; k = ks*16 + (mat>>1)*8 + col
//   tap = k>>7 ; i = k&127 ; h=0 -> bf16 hi, h=1 -> residual lo
__global__ void wsplit(const float* __restrict__ w) {
    int idx = blockIdx.x * blockDim.x + threadIdx.x;
    if (idx < KSTEPS * 8192) {
        int col = idx & 7;
        int row = (idx >> 3) & 7;
        int mat = (idx >> 6) & 3;
        int MT  = (idx >> 8) & 15;
        int h   = (idx >> 12) & 1;
        int ks  = idx >> 13;
        int m = MT * 16 + (mat & 1) * 8 + row;
        int k = ks * 16 + (mat >> 1) * 8 + col;
        int tap = k >> 7, i = k & 127;
        float wv = w[m * (C_IN * 3) + i * 3 + tap];
        unsigned short wh = f2bh(wv);
        g_wA[idx] = h ? f2bh(wv - bh2f(wh)) : wh;
    }
}

// ---------------- K3: conv GEMM via mma.sync bf16 ----------------
// CTA = (b, stroke-pair): M=256 (8 warps x m32), N=64, K=384.
// A streamed PER-WARP through a 4-stage cp.async ring (disjoint slices,
// warp-scope sync only — no __syncthreads in the mainloop).
__global__ __launch_bounds__(256, 1)
void conv_mma_kernel(const float* __restrict__ dense, const float* __restrict__ bias) {
    extern __shared__ __align__(16) unsigned char dsm[];
    int tid = threadIdx.x, lane = tid & 31, w = tid >> 5;
    int cta = blockIdx.x;
    int b = cta >> 4, sp = cta & 15;

    uint32_t sbA = smem_u32(dsm + SB_A);
    uint32_t sbB = smem_u32(dsm + SB_B);
    const char* gA = (const char*)g_wA;

    // per-warp A slice: warp w owns bytes [w*1024, w*1024+1024) of the hi
    // section and the same offsets at +8192 (lo) within each 16KB kstep blk.
    // per lane: 32B hi + 32B lo.
    uint32_t sliceDst = (uint32_t)w * 1024 + (uint32_t)lane * 32;
    size_t   sliceSrc = (size_t)w * 1024 + (size_t)lane * 32;

    // prologue: each warp streams its slices of ksteps 0..2 (3 groups)
#pragma unroll
    for (int pk = 0; pk < 3; pk++) {
        uint32_t dst = sbA + (uint32_t)pk * 16384 + sliceDst;
        const char* src = gA + (size_t)pk * 16384 + sliceSrc;
        CP_ASYNC16(dst, src);
        CP_ASYNC16(dst + 16, src + 16);
        CP_ASYNC16(dst + 8192, src + 8192);
        CP_ASYNC16(dst + 8192 + 16, src + 8192 + 16);
        CP_COMMIT();
    }

    // ---- build B (data) rows: k = tap*128 + i, 128 B/row, xor swizzle ----
    {
        int i = tid & 127, g = tid >> 7;
        int s = sp * 2 + g;
        int sid = g_fps_idx[b * N_HALF + s];
        const float4* r4 = (const float4*)(dense + ((size_t)b * C_IN + i) * (N_STK * N_PNT)
                                           + (size_t)sid * N_PNT);
        char* Bh = (char*)dsm + SB_B;
        char* Bl = (char*)dsm + SB_B + 49152;
        uint32_t kS = i, kU = 128 + i, kV = 256 + i;
        uint32_t swS = (kS & 7) << 4, swU = (kU & 7) << 4, swV = (kV & 7) << 4;
        uint32_t ph = 0, pl = 0;     // prev v (left pad = 0)
#pragma unroll
        for (int q = 0; q < 16; q++) {
            float4 x = r4[q];
            unsigned short u0h = f2bh(x.x), v0h = f2bh(x.y);
            unsigned short u1h = f2bh(x.z), v1h = f2bh(x.w);
            unsigned short u0l = f2bh(x.x - bh2f(u0h));
            unsigned short v0l = f2bh(x.y - bh2f(v0h));
            unsigned short u1l = f2bh(x.z - bh2f(u1h));
            unsigned short v1l = f2bh(x.w - bh2f(v1h));
            uint32_t n2 = (uint32_t)(g * 32 + 2 * q) * 2;   // byte col
            *(uint32_t*)(Bh + kU * 128 + (n2 ^ swU)) = (uint32_t)u0h | ((uint32_t)u1h << 16);
            *(uint32_t*)(Bl + kU * 128 + (n2 ^ swU)) = (uint32_t)u0l | ((uint32_t)u1l << 16);
            *(uint32_t*)(Bh + kV * 128 + (n2 ^ swV)) = (uint32_t)v0h | ((uint32_t)v1h << 16);
            *(uint32_t*)(Bl + kV * 128 + (n2 ^ swV)) = (uint32_t)v0l | ((uint32_t)v1l << 16);
            *(uint32_t*)(Bh + kS * 128 + (n2 ^ swS)) = ph | ((uint32_t)v0h << 16);
            *(uint32_t*)(Bl + kS * 128 + (n2 ^ swS)) = pl | ((uint32_t)v0l << 16);
            ph = v1h; pl = v1l;
        }
    }
    __syncthreads();   // B visible to all warps; no more block syncs until epilogue

    float acc[2][8][4];
#pragma unroll
    for (int mt = 0; mt < 2; mt++)
#pragma unroll
        for (int nt = 0; nt < 8; nt++)
#pragma unroll
            for (int e = 0; e < 4; e++) acc[mt][nt][e] = 0.f;

    int j = lane >> 3;                       // matrix index 0..3
    int krow = (j & 1) * 8 + (lane & 7);     // k within kstep
    int ncol = (j >> 1) * 8;                 // n offset

    for (int ks = 0; ks < KSTEPS; ks++) {
        int buf = ks & 3;
        CP_WAIT2();          // this thread's group ks retired (pending kept at 3)
        __syncwarp();        // warp-local visibility of the warp's own slice

        // prefetch warp slice of kstep ks+3 into buf (ks+3)&3 = (ks-1)&3,
        // which THIS warp finished reading last iteration. commit always.
        if (ks + 3 < KSTEPS) {
            uint32_t dst = sbA + (uint32_t)((ks + 3) & 3) * 16384 + sliceDst;
            const char* src = gA + (size_t)(ks + 3) * 16384 + sliceSrc;
            CP_ASYNC16(dst, src);
            CP_ASYNC16(dst + 16, src + 16);
            CP_ASYNC16(dst + 8192, src + 8192);
            CP_ASYNC16(dst + 8192 + 16, src + 8192 + 16);
        }
        CP_COMMIT();

        // A fragments (hi+lo, 2 m-tiles)
        uint32_t aB = sbA + (uint32_t)buf * 16384 + (uint32_t)(lane >> 3) * 128
                      + (uint32_t)(lane & 7) * 16;
        uint32_t Ah0[4], Ah1[4], Al0[4], Al1[4];
        LDX4(Ah0, aB + (uint32_t)(w * 2 + 0) * 512);
        LDX4(Ah1, aB + (uint32_t)(w * 2 + 1) * 512);
        LDX4(Al0, aB + 8192 + (uint32_t)(w * 2 + 0) * 512);
        LDX4(Al1, aB + 8192 + (uint32_t)(w * 2 + 1) * 512);

        int kk = ks * 16 + krow;
        uint32_t rowb = (uint32_t)kk * 128;
        uint32_t swz = (uint32_t)(kk & 7) << 4;

        uint32_t Bf[4][4];
        // ---- X hi: Wh*Xh + Wl*Xh ----
#pragma unroll
        for (int np = 0; np < 4; np++) {
            uint32_t nb = (uint32_t)((np * 16 + ncol) * 2);
            LDX4T(Bf[np], sbB + rowb + (nb ^ swz));
        }
#pragma unroll
        for (int np = 0; np < 4; np++) {
            MMA(acc[0][np * 2],     Ah0, Bf[np][0], Bf[np][1]);
            MMA(acc[0][np * 2 + 1], Ah0, Bf[np][2], Bf[np][3]);
            MMA(acc[1][np * 2],     Ah1, Bf[np][0], Bf[np][1]);
            MMA(acc[1][np * 2 + 1], Ah1, Bf[np][2], Bf[np][3]);
            MMA(acc[0][np * 2],     Al0, Bf[np][0], Bf[np][1]);
            MMA(acc[0][np * 2 + 1], Al0, Bf[np][2], Bf[np][3]);
            MMA(acc[1][np * 2],     Al1, Bf[np][0], Bf[np][1]);
            MMA(acc[1][np * 2 + 1], Al1, Bf[np][2], Bf[np][3]);
        }
        // ---- X lo: Wh*Xl ----
#pragma unroll
        for (int np = 0; np < 4; np++) {
            uint32_t nb = (uint32_t)((np * 16 + ncol) * 2);
            LDX4T(Bf[np], sbB + 49152 + rowb + (nb ^ swz));
        }
#pragma unroll
        for (int np = 0; np < 4; np++) {
            MMA(acc[0][np * 2],     Ah0, Bf[np][0], Bf[np][1]);
            MMA(acc[0][np * 2 + 1], Ah0, Bf[np][2], Bf[np][3]);
            MMA(acc[1][np * 2],     Ah1, Bf[np][0], Bf[np][1]);
            MMA(acc[1][np * 2 + 1], Ah1, Bf[np][2], Bf[np][3]);
        }
    }
    __syncthreads();

    // ---- epilogue: stage D in smem, then bias + BN partials + store ----
    float* sy = (float*)dsm;    // 256 rows x stride 66 = 67.6 KB
    int r = lane >> 2, c2 = (lane & 3) * 2;
#pragma unroll
    for (int mt = 0; mt < 2; mt++) {
        int m = w * 32 + mt * 16 + r;
#pragma unroll
        for (int nt = 0; nt < 8; nt++) {
            int n = nt * 8 + c2;
            *(float2*)(sy + m * 66 + n)       = make_float2(acc[mt][nt][0], acc[mt][nt][1]);
            *(float2*)(sy + (m + 8) * 66 + n) = make_float2(acc[mt][nt][2], acc[mt][nt][3]);
        }
    }
    __syncthreads();

    {
        int o = tid;
        float bv = bias[o];
        float S = 0.f, Q = 0.f;
        float* row = sy + o * 66;
        float* dst = g_y + ((size_t)b * C_OUT + o) * 1024 + sp * 64;
#pragma unroll
        for (int n = 0; n < 64; n++) {
            float y = row[n] + bv;
            S += y; Q = fmaf(y, y, Q);
            dst[n] = y;
        }
        g_ps[(size_t)cta * C_OUT + o] = make_float2(S, Q);
    }
}

// ---------------- K4: BN finish ---------------------------------
__global__ void bn_finish(const float* __restrict__ gamma, const float* __restrict__ beta) {
    int o = blockIdx.x;
    int t = threadIdx.x;  // 256
    float S = 0.f, Q = 0.f;
    for (int k = t; k < NBLK; k += 256) {
        float2 p = g_ps[(size_t)k * C_OUT + o];
        S += p.x; Q += p.y;
    }
    __shared__ float rs[256], rq[256];
    rs[t] = S; rq[t] = Q;
    __syncthreads();
    for (int st = 128; st > 0; st >>= 1) {
        if (t < st) { rs[t] += rs[t + st]; rq[t] += rq[t + st]; }
        __syncthreads();
    }
    if (t == 0) {
        const float inv_n = 1.f / 65536.f;
        float mean = rs[0] * inv_n;
        float var  = rq[0] * inv_n - mean * mean;
        float r    = rsqrtf(var + 1e-5f);
        float sc   = gamma[o] * r;
        g_scale[o] = sc;
        g_shift[o] = beta[o] - mean * sc;
    }
}

// ---------------- K5: normalize + GELU --------------------------
__device__ __forceinline__ float gelu_f(float x) {
    float z = 0.7978845608028654f * fmaf(0.044715f * x, x * x, x);
    float e = __expf(2.f * z);
    float th = 1.f - __fdividef(2.f, e + 1.f);
    return 0.5f * x * (1.f + th);
}

__global__ void bn_gelu(float* __restrict__ out) {
    int i = blockIdx.x * blockDim.x + threadIdx.x;
    if (i < (BS * C_OUT * 1024) / 4) {
        float4 v = ((const float4*)g_y)[i];
        int o = (i >> 8) & 255;
        float sc = g_scale[o], sh = g_shift[o];
        v.x = gelu_f(fmaf(v.x, sc, sh));
        v.y = gelu_f(fmaf(v.y, sc, sh));
        v.z = gelu_f(fmaf(v.z, sc, sh));
        v.w = gelu_f(fmaf(v.w, sc, sh));
        ((float4*)out)[i] = v;
    }
}

// ---------------- launch ----------------------------------------
extern "C" void kernel_launch(void* const* d_in, const int* in_sizes, int n_in,
                              void* d_out, int out_size) {
    const float* sparse_fea = (const float*)d_in[0];   // [64,256,64]
    const float* dense_fea  = (const float*)d_in[1];   // [64,128,4096]
    const float* stk_coor   = (const float*)d_in[2];   // [64,64,32]
    const float* conv_w     = (const float*)d_in[3];   // [256,128,1,3]
    const float* conv_b     = (const float*)d_in[4];   // [256]
    const float* bn_gamma   = (const float*)d_in[5];   // [256]
    const float* bn_beta    = (const float*)d_in[6];   // [256]

    float* out = (float*)d_out;
    float* sparse_out = out;                            // 524288
    float* dense_out  = out + 524288;                   // 16777216
    float* coor_out   = out + 524288 + 16777216;        // 65536

    cudaFuncSetAttribute(conv_mma_kernel, cudaFuncAttributeMaxDynamicSharedMemorySize, SMEM_TOT);

    fps_kernel<<<BS, N_STK>>>(stk_coor, coor_out);                               // 1
    gather_sparse<<<(BS * SP_EMB * N_HALF + 255) / 256, 256>>>(sparse_fea, sparse_out); // 2
    wsplit<<<(KSTEPS * 8192 + 255) / 256, 256>>>(conv_w);                         // 3
    conv_mma_kernel<<<NBLK, 256, SMEM_TOT>>>(dense_fea, conv_b);                  // 4 (profiled)
    bn_finish<<<C_OUT, 256>>>(bn_gamma, bn_beta);                                 // 5
    bn_gelu<<<(BS * C_OUT * 1024 / 4 + 255) / 256, 256>>>(dense_out);             // 6
}